// round 6
// baseline (speedup 1.0000x reference)
#include <cuda_runtime.h>
#include <cuda_bf16.h>
#include <cuda_fp16.h>
#include <cstdint>

#define N_NODES 50000
#define N_EDGES 800000
#define C 128
#define BN_EPS 1e-5f

// ================= PTX helpers (sm_100-safe: mma.sync / ldmatrix / cp.async) =================
__device__ __forceinline__ uint32_t smem_u32(const void* p) {
    uint32_t a;
    asm("{ .reg .u64 t; cvta.to.shared.u64 t, %1; cvt.u32.u64 %0, t; }" : "=r"(a) : "l"(p));
    return a;
}
__device__ __forceinline__ void cpa16(uint32_t dst, const void* src, uint32_t sz) {
    asm volatile("cp.async.cg.shared.global [%0], [%1], 16, %2;" :: "r"(dst), "l"(src), "r"(sz));
}
#define CP_COMMIT() asm volatile("cp.async.commit_group;" ::: "memory")
__device__ __forceinline__ void ldsm_x4(uint32_t* r, uint32_t a) {
    asm volatile("ldmatrix.sync.aligned.m8n8.x4.shared.b16 {%0,%1,%2,%3}, [%4];"
                 : "=r"(r[0]), "=r"(r[1]), "=r"(r[2]), "=r"(r[3]) : "r"(a));
}
__device__ __forceinline__ void ldsm_x2(uint32_t* r, uint32_t a) {
    asm volatile("ldmatrix.sync.aligned.m8n8.x2.shared.b16 {%0,%1}, [%2];"
                 : "=r"(r[0]), "=r"(r[1]) : "r"(a));
}
__device__ __forceinline__ void mma16816(float* d, const uint32_t* a, const uint32_t* b) {
    asm volatile(
        "mma.sync.aligned.m16n8k16.row.col.f32.bf16.bf16.f32 "
        "{%0,%1,%2,%3},{%4,%5,%6,%7},{%8,%9},{%0,%1,%2,%3};"
        : "+f"(d[0]), "+f"(d[1]), "+f"(d[2]), "+f"(d[3])
        : "r"(a[0]), "r"(a[1]), "r"(a[2]), "r"(a[3]), "r"(b[0]), "r"(b[1]));
}

// ================= scratch =================
__device__ __align__(16) int   g_off[N_NODES + 4];
__device__ __align__(16) int   g_cursor[N_NODES + 4];
__device__ int2  g_edge[N_EDGES];             // packed (src, weight-bits)
__device__ float g_h[N_NODES * C];
__device__ __half g_xf[N_NODES * C];          // fp16 features (gather + residual)
__device__ __nv_bfloat16 g_xh[N_NODES * C];   // bf16 hi (GEMM X operand)
__device__ __nv_bfloat16 g_xl[N_NODES * C];   // bf16 lo
__device__ __nv_bfloat16 g_aggh[N_NODES * C];
__device__ __nv_bfloat16 g_aggl[N_NODES * C];
// B slices per layer: id = path*4 + lo*2 + khalf, 8 slices of [NN][64] bf16
__device__ __nv_bfloat16 g_bt0[8 * 128 * 64];
__device__ __nv_bfloat16 g_bt1[8 * 128 * 64];
__device__ __nv_bfloat16 g_bt2[8 * 64 * 64];
__device__ float g_sum[2 * C];
__device__ float g_sumsq[2 * C];

// ================= helpers =================
__device__ __forceinline__ void split_store4(float4 v, __nv_bfloat16* ph, __nv_bfloat16* pl) {
    __nv_bfloat16 hx = __float2bfloat16_rn(v.x), hy = __float2bfloat16_rn(v.y),
                  hz = __float2bfloat16_rn(v.z), hw = __float2bfloat16_rn(v.w);
    __nv_bfloat16 lx = __float2bfloat16_rn(v.x - __bfloat162float(hx)),
                  ly = __float2bfloat16_rn(v.y - __bfloat162float(hy)),
                  lz = __float2bfloat16_rn(v.z - __bfloat162float(hz)),
                  lw = __float2bfloat16_rn(v.w - __bfloat162float(hw));
    __nv_bfloat162 h0 = __halves2bfloat162(hx, hy), h1 = __halves2bfloat162(hz, hw);
    __nv_bfloat162 l0 = __halves2bfloat162(lx, ly), l1 = __halves2bfloat162(lz, lw);
    *(uint2*)ph = make_uint2(*(uint32_t*)&h0, *(uint32_t*)&h1);
    *(uint2*)pl = make_uint2(*(uint32_t*)&l0, *(uint32_t*)&l1);
}
__device__ __forceinline__ void half_store4(float4 v, __half* pf) {
    __half2 a = __floats2half2_rn(v.x, v.y);
    __half2 b = __floats2half2_rn(v.z, v.w);
    *(uint2*)pf = make_uint2(*(uint32_t*)&a, *(uint32_t*)&b);
}
__device__ __forceinline__ float2 h2f2(uint32_t h) {
    return __half22float2(*(__half2*)&h);
}

// ================= setup: zero counters/stats + split input x =================
__global__ void setup_kernel(const float* __restrict__ x) {
    int i = blockIdx.x * blockDim.x + threadIdx.x;
    if (i <= N_NODES) g_off[i] = 0;
    if (i < 2 * C) { g_sum[i] = 0.f; g_sumsq[i] = 0.f; }
    if (i < N_NODES * (C / 4)) {
        float4 v = ((const float4*)x)[i];
        split_store4(v, g_xh + (size_t)i * 4, g_xl + (size_t)i * 4);
        half_store4(v, g_xf + (size_t)i * 4);
    }
}

__global__ void hist_kernel(const int* __restrict__ dst) {
    int e = blockIdx.x * blockDim.x + threadIdx.x;
    if (e < N_EDGES) atomicAdd(&g_off[dst[e]], 1);
}

// single-block scan, 4 elems/thread
__global__ void scan_kernel() {
    __shared__ int warp_sums[32];
    __shared__ int carry;
    const int tid = threadIdx.x;
    const int lane = tid & 31;
    const int wid = tid >> 5;
    if (tid == 0) carry = 0;
    __syncthreads();
    for (int base = 0; base < N_NODES; base += 4096) {
        int i0 = base + tid * 4;
        int v0 = 0, v1 = 0, v2 = 0, v3 = 0;
        if (i0 + 3 < N_NODES) {
            int4 t = *(const int4*)(g_off + i0);
            v0 = t.x; v1 = t.y; v2 = t.z; v3 = t.w;
        } else {
            if (i0 < N_NODES) v0 = g_off[i0];
            if (i0 + 1 < N_NODES) v1 = g_off[i0 + 1];
            if (i0 + 2 < N_NODES) v2 = g_off[i0 + 2];
            if (i0 + 3 < N_NODES) v3 = g_off[i0 + 3];
        }
        int t = v0 + v1 + v2 + v3;
        int x = t;
        #pragma unroll
        for (int s = 1; s < 32; s <<= 1) {
            int u = __shfl_up_sync(0xFFFFFFFFu, x, s);
            if (lane >= s) x += u;
        }
        if (lane == 31) warp_sums[wid] = x;
        __syncthreads();
        if (wid == 0) {
            int ws = warp_sums[lane];
            #pragma unroll
            for (int s = 1; s < 32; s <<= 1) {
                int u = __shfl_up_sync(0xFFFFFFFFu, ws, s);
                if (lane >= s) ws += u;
            }
            warp_sums[lane] = ws;
        }
        __syncthreads();
        int excl = carry + (wid ? warp_sums[wid - 1] : 0) + (x - t);
        int e0 = excl, e1 = excl + v0, e2 = e1 + v1, e3 = e2 + v2;
        if (i0 + 3 < N_NODES) {
            *(int4*)(g_off + i0) = make_int4(e0, e1, e2, e3);
            *(int4*)(g_cursor + i0) = make_int4(e0, e1, e2, e3);
        } else {
            if (i0 < N_NODES) { g_off[i0] = e0; g_cursor[i0] = e0; }
            if (i0 + 1 < N_NODES) { g_off[i0 + 1] = e1; g_cursor[i0 + 1] = e1; }
            if (i0 + 2 < N_NODES) { g_off[i0 + 2] = e2; g_cursor[i0 + 2] = e2; }
        }
        __syncthreads();
        if (tid == 0) carry += warp_sums[31];
        __syncthreads();
    }
    if (tid == 0) g_off[N_NODES] = carry;
}

__global__ void build_csr_kernel(const int* __restrict__ src,
                                 const int* __restrict__ dst,
                                 const float* __restrict__ w) {
    int e = blockIdx.x * blockDim.x + threadIdx.x;
    if (e < N_EDGES) {
        int d = dst[e];
        int p = atomicAdd(&g_cursor[d], 1);
        g_edge[p] = make_int2(src[e], __float_as_int(w[e]));
    }
}

// ================= B-tiles: 8 unique slices per layer, all 3 layers in one kernel =================
// slice id = path*4 + lo*2 + khalf; layout [NN rows(n)][64 cols(k)] bf16 dense.
template <int NN>
__device__ __forceinline__ void bt_fill(int idx, const float* Wrel, const float* Wroot,
                                        __nv_bfloat16* Bt) {
    int s = idx / (NN * 64);
    int r = idx % (NN * 64);
    int n = r / 64;
    int kk = r % 64;
    int path = s >> 2;
    bool lo = (s >> 1) & 1;
    int kh = s & 1;
    const float* W = path ? Wroot : Wrel;
    float w = W[(size_t)(kh * 64 + kk) * NN + n];
    __nv_bfloat16 hv = __float2bfloat16_rn(w);
    Bt[(size_t)s * NN * 64 + n * 64 + kk] =
        lo ? __float2bfloat16_rn(w - __bfloat162float(hv)) : hv;
}
__global__ void build_bt_all(const float* __restrict__ Wr0, const float* __restrict__ Wo0,
                             const float* __restrict__ Wr1, const float* __restrict__ Wo1,
                             const float* __restrict__ Wr2, const float* __restrict__ Wo2) {
    int idx = blockIdx.x * 256 + threadIdx.x;
    const int B128 = 8 * 128 * 64;
    const int B64 = 8 * 64 * 64;
    if (idx < B128) bt_fill<128>(idx, Wr0, Wo0, g_bt0);
    else if (idx < 2 * B128) bt_fill<128>(idx - B128, Wr1, Wo1, g_bt1);
    else if (idx < 2 * B128 + B64) bt_fill<64>(idx - 2 * B128, Wr2, Wo2, g_bt2);
}

// ================= aggregation: one warp/node, fp16 gather, packed edges =================
__global__ void aggregate_kernel() {
    int gw = (blockIdx.x * blockDim.x + threadIdx.x) >> 5;
    int lane = threadIdx.x & 31;
    if (gw >= N_NODES) return;
    int j = g_off[gw];
    int e = g_off[gw + 1];
    float4 acc = make_float4(0.f, 0.f, 0.f, 0.f);
    const __half* xf = g_xf;
    for (; j + 3 < e; j += 4) {
        int2 e0 = g_edge[j], e1 = g_edge[j + 1], e2 = g_edge[j + 2], e3 = g_edge[j + 3];
        uint2 r0 = __ldg((const uint2*)(xf + (size_t)e0.x * C) + lane);
        uint2 r1 = __ldg((const uint2*)(xf + (size_t)e1.x * C) + lane);
        uint2 r2 = __ldg((const uint2*)(xf + (size_t)e2.x * C) + lane);
        uint2 r3 = __ldg((const uint2*)(xf + (size_t)e3.x * C) + lane);
        float w0 = __int_as_float(e0.y), w1 = __int_as_float(e1.y);
        float w2 = __int_as_float(e2.y), w3 = __int_as_float(e3.y);
        float2 a, b;
        a = h2f2(r0.x); b = h2f2(r0.y);
        acc.x = fmaf(w0, a.x, acc.x); acc.y = fmaf(w0, a.y, acc.y);
        acc.z = fmaf(w0, b.x, acc.z); acc.w = fmaf(w0, b.y, acc.w);
        a = h2f2(r1.x); b = h2f2(r1.y);
        acc.x = fmaf(w1, a.x, acc.x); acc.y = fmaf(w1, a.y, acc.y);
        acc.z = fmaf(w1, b.x, acc.z); acc.w = fmaf(w1, b.y, acc.w);
        a = h2f2(r2.x); b = h2f2(r2.y);
        acc.x = fmaf(w2, a.x, acc.x); acc.y = fmaf(w2, a.y, acc.y);
        acc.z = fmaf(w2, b.x, acc.z); acc.w = fmaf(w2, b.y, acc.w);
        a = h2f2(r3.x); b = h2f2(r3.y);
        acc.x = fmaf(w3, a.x, acc.x); acc.y = fmaf(w3, a.y, acc.y);
        acc.z = fmaf(w3, b.x, acc.z); acc.w = fmaf(w3, b.y, acc.w);
    }
    for (; j < e; j++) {
        int2 ed = g_edge[j];
        float w = __int_as_float(ed.y);
        uint2 r = __ldg((const uint2*)(xf + (size_t)ed.x * C) + lane);
        float2 a = h2f2(r.x), b = h2f2(r.y);
        acc.x = fmaf(w, a.x, acc.x); acc.y = fmaf(w, a.y, acc.y);
        acc.z = fmaf(w, b.x, acc.z); acc.w = fmaf(w, b.y, acc.w);
    }
    size_t base = (size_t)gw * C + lane * 4;
    split_store4(acc, g_aggh + base, g_aggl + base);
}

// ================= HMMA GEMM with operand-dedup schedule =================
// 4 groups (path x khalf), each 3 iters: {hi*Wh, lo*Wh (B reuse), hi*Wl (A reuse)}.
// Slots: hiA[2] (rotating per group), loA, Wh[2] (rotating), Wl. 8 A-loads, 8 B-loads.
template <int NN, bool STATS>
__global__ void __launch_bounds__(256) mma_gemm_kernel(
    const __nv_bfloat16* __restrict__ Ah, const __nv_bfloat16* __restrict__ Al,
    const __nv_bfloat16* __restrict__ Xh, const __nv_bfloat16* __restrict__ Xl,
    const __nv_bfloat16* __restrict__ Bt,
    const float* __restrict__ bias, float* __restrict__ H, int layer) {
    constexpr int WM = (NN == 128) ? 2 : 4;
    constexpr int WN = 8 / WM;
    constexpr int MF = 128 / (WM * 16);
    constexpr int NF = NN / (WN * 8);
    constexpr int PITCH = 144;
    constexpr int ABYTES = 128 * PITCH;
    constexpr int BBYTES = NN * PITCH;

    extern __shared__ __align__(16) char smem[];
    const uint32_t sb = smem_u32(smem);
    const uint32_t hiS[2] = {sb, sb + ABYTES};
    const uint32_t loS = sb + 2 * ABYTES;
    const uint32_t whS[2] = {sb + 3 * ABYTES, sb + 3 * ABYTES + BBYTES};
    const uint32_t wlS = sb + 3 * ABYTES + 2 * BBYTES;
    __shared__ float ssum[NN], ssq[NN];

    const int tid = threadIdx.x;
    const int wid = tid >> 5;
    const int lane = tid & 31;
    const int m0 = blockIdx.x * 128;
    const int wmb = (wid / WN) * (MF * 16);
    const int wnb = (wid % WN) * (NF * 8);

    // per-group A sources: path = g>>1, kh = g&1
    const __nv_bfloat16* hiSrc[4] = {Ah, Ah, Xh, Xh};
    const __nv_bfloat16* loSrc[4] = {Al, Al, Xl, Xl};

    float acc[MF][NF][4];
    #pragma unroll
    for (int i = 0; i < MF; i++)
        #pragma unroll
        for (int j = 0; j < NF; j++)
            #pragma unroll
            for (int k = 0; k < 4; k++) acc[i][j][k] = 0.f;

    auto load_A = [&](uint32_t slot, const __nv_bfloat16* As, int kh) {
        #pragma unroll
        for (int u = 0; u < 4; u++) {
            int unit = tid + u * 256;
            int row = unit >> 3, cu = unit & 7;
            int m = m0 + row;
            cpa16(slot + row * PITCH + cu * 16,
                  (const char*)(As + (size_t)m * C + kh * 64) + cu * 16,
                  (m < N_NODES) ? 16u : 0u);
        }
    };
    auto load_B = [&](uint32_t slot, int slice) {
        const char* Bs = (const char*)(Bt + (size_t)slice * NN * 64);
        #pragma unroll
        for (int u = 0; u < NN / 32; u++) {
            int unit = tid + u * 256;
            int n = unit >> 3, cu = unit & 7;
            cpa16(slot + n * PITCH + cu * 16, Bs + n * 128 + cu * 16, 16u);
        }
    };
    // prefetch the loads needed by iteration `it`
    auto prefetch = [&](int it) {
        int g = it / 3, j = it % 3;
        int path = g >> 1, kh = g & 1;
        if (j == 0) {
            load_A(hiS[g & 1], hiSrc[g], kh);
            load_B(whS[g & 1], path * 4 + kh);          // Wh slice
        } else if (j == 1) {
            load_A(loS, loSrc[g], kh);
        } else {
            load_B(wlS, path * 4 + 2 + kh);             // Wl slice
        }
    };

    const uint32_t a_lane = (lane & 7) * PITCH + ((lane >> 3) & 1) * 8 * PITCH + (lane >> 4) * 16;
    const uint32_t b_lane = (lane & 7) * PITCH + (((lane & 15) >> 3)) * 16;

    prefetch(0);
    CP_COMMIT();
    #pragma unroll
    for (int it = 0; it < 12; it++) {
        if (it < 11) {
            prefetch(it + 1);
            CP_COMMIT();
            asm volatile("cp.async.wait_group 1;" ::: "memory");
        } else {
            asm volatile("cp.async.wait_group 0;" ::: "memory");
        }
        __syncthreads();
        int g = it / 3, j = it % 3;
        uint32_t aslot = (j == 1) ? loS : hiS[g & 1];
        uint32_t bslot = (j == 2) ? wlS : whS[g & 1];
        uint32_t abase = aslot + wmb * PITCH + a_lane;
        uint32_t bbase = bslot + wnb * PITCH + b_lane;
        #pragma unroll
        for (int ks = 0; ks < 4; ks++) {
            uint32_t a[MF][4], b[NF][2];
            #pragma unroll
            for (int mf = 0; mf < MF; mf++) ldsm_x4(a[mf], abase + mf * 16 * PITCH + ks * 32);
            #pragma unroll
            for (int nf = 0; nf < NF; nf++) ldsm_x2(b[nf], bbase + nf * 8 * PITCH + ks * 32);
            #pragma unroll
            for (int mf = 0; mf < MF; mf++)
                #pragma unroll
                for (int nf = 0; nf < NF; nf++) mma16816(acc[mf][nf], a[mf], b[nf]);
        }
    }
    __syncthreads();

    if (STATS) {
        if (tid < NN) { ssum[tid] = 0.f; ssq[tid] = 0.f; }
        __syncthreads();
    }

    #pragma unroll
    for (int mf = 0; mf < MF; mf++) {
        int r = m0 + wmb + mf * 16 + (lane >> 2);
        #pragma unroll
        for (int nf = 0; nf < NF; nf++) {
            int cc = wnb + nf * 8 + (lane & 3) * 2;
            float b0 = bias ? bias[cc] : 0.f;
            float b1 = bias ? bias[cc + 1] : 0.f;
            if (r < N_NODES)
                *(float2*)(H + (size_t)r * NN + cc) =
                    make_float2(acc[mf][nf][0] + b0, acc[mf][nf][1] + b1);
            if (r + 8 < N_NODES)
                *(float2*)(H + (size_t)(r + 8) * NN + cc) =
                    make_float2(acc[mf][nf][2] + b0, acc[mf][nf][3] + b1);
        }
    }

    if (STATS) {
        // OOB rows hold zeros (cp.async zfill) -> contribute nothing
        #pragma unroll
        for (int nf = 0; nf < NF; nf++) {
            #pragma unroll
            for (int j = 0; j < 2; j++) {
                int col = wnb + nf * 8 + (lane & 3) * 2 + j;
                float s = 0.f, q = 0.f;
                #pragma unroll
                for (int mf = 0; mf < MF; mf++) {
                    float v0 = acc[mf][nf][j];
                    float v1 = acc[mf][nf][2 + j];
                    s += v0 + v1;
                    q += v0 * v0 + v1 * v1;
                }
                atomicAdd(&ssum[col], s);
                atomicAdd(&ssq[col], q);
            }
        }
        __syncthreads();
        if (tid < NN) {
            atomicAdd(&g_sum[layer * C + tid], ssum[tid]);
            atomicAdd(&g_sumsq[layer * C + tid], ssq[tid]);
        }
    }
}

// ================= BN apply (finalize fused): in-place feature update =================
// o = relu(h*scale + shift + residual); residual from fp16 xf; writes xf/xh/xl.
__global__ void bn_apply_kernel(const float* __restrict__ h,
                                const float* __restrict__ gamma,
                                const float* __restrict__ beta, int layer) {
    int i = blockIdx.x * blockDim.x + threadIdx.x;
    if (i >= N_NODES * (C / 4)) return;
    int c = (i & 31) << 2;
    float4 sm = *(const float4*)(g_sum + layer * C + c);
    float4 sq = *(const float4*)(g_sumsq + layer * C + c);
    float4 gm = *(const float4*)(gamma + c);
    float4 bt = *(const float4*)(beta + c);
    const float inv = 1.f / N_NODES;
    float mx = sm.x * inv, my = sm.y * inv, mz = sm.z * inv, mw = sm.w * inv;
    float scx = gm.x * rsqrtf(sq.x * inv - mx * mx + BN_EPS);
    float scy = gm.y * rsqrtf(sq.y * inv - my * my + BN_EPS);
    float scz = gm.z * rsqrtf(sq.z * inv - mz * mz + BN_EPS);
    float scw = gm.w * rsqrtf(sq.w * inv - mw * mw + BN_EPS);
    float shx = bt.x - mx * scx, shy = bt.y - my * scy;
    float shz = bt.z - mz * scz, shw = bt.w - mw * scw;

    float4 hv = ((const float4*)h)[i];
    uint2 xr = *(const uint2*)(g_xf + (size_t)i * 4);
    float2 xa = h2f2(xr.x), xb = h2f2(xr.y);
    float4 o;
    o.x = fmaxf(fmaf(hv.x, scx, shx) + xa.x, 0.f);
    o.y = fmaxf(fmaf(hv.y, scy, shy) + xa.y, 0.f);
    o.z = fmaxf(fmaf(hv.z, scz, shz) + xb.x, 0.f);
    o.w = fmaxf(fmaf(hv.w, scw, shw) + xb.y, 0.f);
    split_store4(o, g_xh + (size_t)i * 4, g_xl + (size_t)i * 4);
    half_store4(o, g_xf + (size_t)i * 4);
}

// ================= launch =================
extern "C" void kernel_launch(void* const* d_in, const int* in_sizes, int n_in,
                              void* d_out, int out_size) {
    const float* x    = (const float*)d_in[0];
    const int*   esrc = (const int*)d_in[1];
    const int*   edst = (const int*)d_in[2];
    const float* ew   = (const float*)d_in[3];
    const float* Wr0  = (const float*)d_in[4];
    // b_rel0 (d_in[5]) cancels exactly under BN
    const float* Wo0  = (const float*)d_in[6];
    const float* Wr1  = (const float*)d_in[7];
    // b_rel1 (d_in[8]) cancels under BN
    const float* Wo1  = (const float*)d_in[9];
    const float* Wr2  = (const float*)d_in[10];
    const float* b2   = (const float*)d_in[11];
    const float* Wo2  = (const float*)d_in[12];
    const float* gamma0 = (const float*)d_in[13];
    const float* beta0  = (const float*)d_in[14];
    const float* gamma1 = (const float*)d_in[15];
    const float* beta1  = (const float*)d_in[16];
    float* out = (float*)d_out;

    float* h;
    __nv_bfloat16 *aggh, *aggl, *xh, *xl, *bt0, *bt1, *bt2;
    cudaGetSymbolAddress((void**)&h, g_h);
    cudaGetSymbolAddress((void**)&aggh, g_aggh);
    cudaGetSymbolAddress((void**)&aggl, g_aggl);
    cudaGetSymbolAddress((void**)&xh, g_xh);
    cudaGetSymbolAddress((void**)&xl, g_xl);
    cudaGetSymbolAddress((void**)&bt0, g_bt0);
    cudaGetSymbolAddress((void**)&bt1, g_bt1);
    cudaGetSymbolAddress((void**)&bt2, g_bt2);

    // smem: 3 A slots + 3 B slots
    const int SMEM128 = 3 * 128 * 144 + 3 * 128 * 144;  // 110592
    const int SMEM64  = 3 * 128 * 144 + 3 * 64 * 144;   // 82944
    cudaFuncSetAttribute(mma_gemm_kernel<128, true>,
                         cudaFuncAttributeMaxDynamicSharedMemorySize, SMEM128);
    cudaFuncSetAttribute(mma_gemm_kernel<64, false>,
                         cudaFuncAttributeMaxDynamicSharedMemorySize, SMEM64);

    const int EB = (N_EDGES + 255) / 256;
    const int AGG_B = (N_NODES + 7) / 8;
    const int GEMM_B = (N_NODES + 127) / 128;
    const int APPLY_B = (N_NODES * (C / 4) + 255) / 256;
    const int BT_TOTAL = 2 * (8 * 128 * 64) + 8 * 64 * 64;

    setup_kernel<<<APPLY_B, 256>>>(x);
    hist_kernel<<<EB, 256>>>(edst);
    scan_kernel<<<1, 1024>>>();
    build_csr_kernel<<<EB, 256>>>(esrc, edst, ew);
    build_bt_all<<<(BT_TOTAL + 255) / 256, 256>>>(Wr0, Wo0, Wr1, Wo1, Wr2, Wo2);

    // ---- layer 0 ----
    aggregate_kernel<<<AGG_B, 256>>>();
    mma_gemm_kernel<128, true><<<GEMM_B, 256, SMEM128>>>(aggh, aggl, xh, xl, bt0, nullptr, h, 0);
    bn_apply_kernel<<<APPLY_B, 256>>>(h, gamma0, beta0, 0);

    // ---- layer 1 ----
    aggregate_kernel<<<AGG_B, 256>>>();
    mma_gemm_kernel<128, true><<<GEMM_B, 256, SMEM128>>>(aggh, aggl, xh, xl, bt1, nullptr, h, 1);
    bn_apply_kernel<<<APPLY_B, 256>>>(h, gamma1, beta1, 1);

    // ---- layer 2 ----
    aggregate_kernel<<<AGG_B, 256>>>();
    mma_gemm_kernel<64, false><<<GEMM_B, 256, SMEM64>>>(aggh, aggl, xh, xl, bt2, b2, out, 0);
}

// round 7
// speedup vs baseline: 1.1167x; 1.1167x over previous
#include <cuda_runtime.h>
#include <cuda_fp16.h>
#include <cstdint>

#define N_NODES 50000
#define N_EDGES 800000
#define C 128
#define BN_EPS 1e-5f

// ================= PTX helpers (sm_100-safe: mma.sync / ldmatrix / cp.async) =================
__device__ __forceinline__ uint32_t smem_u32(const void* p) {
    uint32_t a;
    asm("{ .reg .u64 t; cvta.to.shared.u64 t, %1; cvt.u32.u64 %0, t; }" : "=r"(a) : "l"(p));
    return a;
}
__device__ __forceinline__ void cpa16(uint32_t dst, const void* src, uint32_t sz) {
    asm volatile("cp.async.cg.shared.global [%0], [%1], 16, %2;" :: "r"(dst), "l"(src), "r"(sz));
}
#define CP_COMMIT() asm volatile("cp.async.commit_group;" ::: "memory")
__device__ __forceinline__ void ldsm_x4(uint32_t* r, uint32_t a) {
    asm volatile("ldmatrix.sync.aligned.m8n8.x4.shared.b16 {%0,%1,%2,%3}, [%4];"
                 : "=r"(r[0]), "=r"(r[1]), "=r"(r[2]), "=r"(r[3]) : "r"(a));
}
__device__ __forceinline__ void ldsm_x2(uint32_t* r, uint32_t a) {
    asm volatile("ldmatrix.sync.aligned.m8n8.x2.shared.b16 {%0,%1}, [%2];"
                 : "=r"(r[0]), "=r"(r[1]) : "r"(a));
}
__device__ __forceinline__ void mma16816(float* d, const uint32_t* a, const uint32_t* b) {
    asm volatile(
        "mma.sync.aligned.m16n8k16.row.col.f32.f16.f16.f32 "
        "{%0,%1,%2,%3},{%4,%5,%6,%7},{%8,%9},{%0,%1,%2,%3};"
        : "+f"(d[0]), "+f"(d[1]), "+f"(d[2]), "+f"(d[3])
        : "r"(a[0]), "r"(a[1]), "r"(a[2]), "r"(a[3]), "r"(b[0]), "r"(b[1]));
}

// ================= scratch =================
__device__ __align__(16) int   g_off[N_NODES + 4];
__device__ __align__(16) int   g_cursor[N_NODES + 4];
__device__ int2  g_edge[N_EDGES];        // packed (src, weight-bits)
__device__ float g_h[N_NODES * C];
__device__ __half g_xf[N_NODES * C];     // fp16 features (gather + GEMM X operand + residual)
__device__ __half g_aggf[N_NODES * C];   // fp16 aggregation result (GEMM A operand)
// B slices per layer: id = path*4 + wsplit*2 + khalf -> 8 slices of [NN][64] fp16
__device__ __half g_bt0[8 * 128 * 64];
__device__ __half g_bt1[8 * 128 * 64];
__device__ __half g_bt2[8 * 64 * 64];
__device__ float g_sum[2 * C];
__device__ float g_sumsq[2 * C];

// ================= helpers =================
__device__ __forceinline__ void half_store4(float4 v, __half* pf) {
    __half2 a = __floats2half2_rn(v.x, v.y);
    __half2 b = __floats2half2_rn(v.z, v.w);
    *(uint2*)pf = make_uint2(*(uint32_t*)&a, *(uint32_t*)&b);
}
__device__ __forceinline__ float2 h2f2(uint32_t h) {
    return __half22float2(*(__half2*)&h);
}

// ================= setup: zero counters/stats + fp16 input =================
__global__ void setup_kernel(const float* __restrict__ x) {
    int i = blockIdx.x * blockDim.x + threadIdx.x;
    if (i <= N_NODES) g_off[i] = 0;
    if (i < 2 * C) { g_sum[i] = 0.f; g_sumsq[i] = 0.f; }
    if (i < N_NODES * (C / 4)) {
        float4 v = ((const float4*)x)[i];
        half_store4(v, g_xf + (size_t)i * 4);
    }
}

__global__ void hist_kernel(const int* __restrict__ dst) {
    int e = blockIdx.x * blockDim.x + threadIdx.x;
    if (e < N_EDGES) atomicAdd(&g_off[dst[e]], 1);
}

// single-block scan, 4 elems/thread
__global__ void scan_kernel() {
    __shared__ int warp_sums[32];
    __shared__ int carry;
    const int tid = threadIdx.x;
    const int lane = tid & 31;
    const int wid = tid >> 5;
    if (tid == 0) carry = 0;
    __syncthreads();
    for (int base = 0; base < N_NODES; base += 4096) {
        int i0 = base + tid * 4;
        int v0 = 0, v1 = 0, v2 = 0, v3 = 0;
        if (i0 + 3 < N_NODES) {
            int4 t = *(const int4*)(g_off + i0);
            v0 = t.x; v1 = t.y; v2 = t.z; v3 = t.w;
        } else {
            if (i0 < N_NODES) v0 = g_off[i0];
            if (i0 + 1 < N_NODES) v1 = g_off[i0 + 1];
            if (i0 + 2 < N_NODES) v2 = g_off[i0 + 2];
            if (i0 + 3 < N_NODES) v3 = g_off[i0 + 3];
        }
        int t = v0 + v1 + v2 + v3;
        int x = t;
        #pragma unroll
        for (int s = 1; s < 32; s <<= 1) {
            int u = __shfl_up_sync(0xFFFFFFFFu, x, s);
            if (lane >= s) x += u;
        }
        if (lane == 31) warp_sums[wid] = x;
        __syncthreads();
        if (wid == 0) {
            int ws = warp_sums[lane];
            #pragma unroll
            for (int s = 1; s < 32; s <<= 1) {
                int u = __shfl_up_sync(0xFFFFFFFFu, ws, s);
                if (lane >= s) ws += u;
            }
            warp_sums[lane] = ws;
        }
        __syncthreads();
        int excl = carry + (wid ? warp_sums[wid - 1] : 0) + (x - t);
        int e0 = excl, e1 = excl + v0, e2 = e1 + v1, e3 = e2 + v2;
        if (i0 + 3 < N_NODES) {
            *(int4*)(g_off + i0) = make_int4(e0, e1, e2, e3);
            *(int4*)(g_cursor + i0) = make_int4(e0, e1, e2, e3);
        } else {
            if (i0 < N_NODES) { g_off[i0] = e0; g_cursor[i0] = e0; }
            if (i0 + 1 < N_NODES) { g_off[i0 + 1] = e1; g_cursor[i0 + 1] = e1; }
            if (i0 + 2 < N_NODES) { g_off[i0 + 2] = e2; g_cursor[i0 + 2] = e2; }
        }
        __syncthreads();
        if (tid == 0) carry += warp_sums[31];
        __syncthreads();
    }
    if (tid == 0) g_off[N_NODES] = carry;
}

__global__ void build_csr_kernel(const int* __restrict__ src,
                                 const int* __restrict__ dst,
                                 const float* __restrict__ w) {
    int e = blockIdx.x * blockDim.x + threadIdx.x;
    if (e < N_EDGES) {
        int d = dst[e];
        int p = atomicAdd(&g_cursor[d], 1);
        g_edge[p] = make_int2(src[e], __float_as_int(w[e]));
    }
}

// ================= B-tiles: 8 fp16 slices per layer (W hi/lo), all layers in one =================
// slice id = path*4 + ws*2 + kh; layout [NN rows(n)][64 cols(k)] fp16 dense.
template <int NN>
__device__ __forceinline__ void bt_fill(int idx, const float* Wrel, const float* Wroot,
                                        __half* Bt) {
    int s = idx / (NN * 64);
    int r = idx % (NN * 64);
    int n = r / 64;
    int kk = r % 64;
    int path = s >> 2;
    bool lo = (s >> 1) & 1;
    int kh = s & 1;
    const float* W = path ? Wroot : Wrel;
    float w = W[(size_t)(kh * 64 + kk) * NN + n];
    __half hv = __float2half_rn(w);
    Bt[(size_t)s * NN * 64 + n * 64 + kk] = lo ? __float2half_rn(w - __half2float(hv)) : hv;
}
__global__ void build_bt_all(const float* __restrict__ Wr0, const float* __restrict__ Wo0,
                             const float* __restrict__ Wr1, const float* __restrict__ Wo1,
                             const float* __restrict__ Wr2, const float* __restrict__ Wo2) {
    int idx = blockIdx.x * 256 + threadIdx.x;
    const int B128 = 8 * 128 * 64;
    const int B64 = 8 * 64 * 64;
    if (idx < B128) bt_fill<128>(idx, Wr0, Wo0, g_bt0);
    else if (idx < 2 * B128) bt_fill<128>(idx - B128, Wr1, Wo1, g_bt1);
    else if (idx < 2 * B128 + B64) bt_fill<64>(idx - 2 * B128, Wr2, Wo2, g_bt2);
}

// ================= aggregation: one warp/node, fp16 gather, fp16 result =================
__global__ void aggregate_kernel() {
    int gw = (blockIdx.x * blockDim.x + threadIdx.x) >> 5;
    int lane = threadIdx.x & 31;
    if (gw >= N_NODES) return;
    int j = g_off[gw];
    int e = g_off[gw + 1];
    float4 acc = make_float4(0.f, 0.f, 0.f, 0.f);
    const __half* xf = g_xf;
    for (; j + 3 < e; j += 4) {
        int2 e0 = g_edge[j], e1 = g_edge[j + 1], e2 = g_edge[j + 2], e3 = g_edge[j + 3];
        uint2 r0 = __ldg((const uint2*)(xf + (size_t)e0.x * C) + lane);
        uint2 r1 = __ldg((const uint2*)(xf + (size_t)e1.x * C) + lane);
        uint2 r2 = __ldg((const uint2*)(xf + (size_t)e2.x * C) + lane);
        uint2 r3 = __ldg((const uint2*)(xf + (size_t)e3.x * C) + lane);
        float w0 = __int_as_float(e0.y), w1 = __int_as_float(e1.y);
        float w2 = __int_as_float(e2.y), w3 = __int_as_float(e3.y);
        float2 a, b;
        a = h2f2(r0.x); b = h2f2(r0.y);
        acc.x = fmaf(w0, a.x, acc.x); acc.y = fmaf(w0, a.y, acc.y);
        acc.z = fmaf(w0, b.x, acc.z); acc.w = fmaf(w0, b.y, acc.w);
        a = h2f2(r1.x); b = h2f2(r1.y);
        acc.x = fmaf(w1, a.x, acc.x); acc.y = fmaf(w1, a.y, acc.y);
        acc.z = fmaf(w1, b.x, acc.z); acc.w = fmaf(w1, b.y, acc.w);
        a = h2f2(r2.x); b = h2f2(r2.y);
        acc.x = fmaf(w2, a.x, acc.x); acc.y = fmaf(w2, a.y, acc.y);
        acc.z = fmaf(w2, b.x, acc.z); acc.w = fmaf(w2, b.y, acc.w);
        a = h2f2(r3.x); b = h2f2(r3.y);
        acc.x = fmaf(w3, a.x, acc.x); acc.y = fmaf(w3, a.y, acc.y);
        acc.z = fmaf(w3, b.x, acc.z); acc.w = fmaf(w3, b.y, acc.w);
    }
    for (; j < e; j++) {
        int2 ed = g_edge[j];
        float w = __int_as_float(ed.y);
        uint2 r = __ldg((const uint2*)(xf + (size_t)ed.x * C) + lane);
        float2 a = h2f2(r.x), b = h2f2(r.y);
        acc.x = fmaf(w, a.x, acc.x); acc.y = fmaf(w, a.y, acc.y);
        acc.z = fmaf(w, b.x, acc.z); acc.w = fmaf(w, b.y, acc.w);
    }
    half_store4(acc, g_aggf + (size_t)gw * C + lane * 4);
}

// ================= HMMA GEMM: H[128,NN] = agg@Wrel + x@Wroot (fp16 A, W hi+lo) =================
// 8 iters of K=64: it -> path = it>>2 (0 agg, 1 x), ws = (it>>1)&1, kh = it&1; B slice = it.
template <int NN, bool STATS>
__global__ void __launch_bounds__(256) mma_gemm_kernel(
    const __half* __restrict__ Af, const __half* __restrict__ Xf,
    const __half* __restrict__ Bt,
    const float* __restrict__ bias, float* __restrict__ H, int layer) {
    constexpr int WM = (NN == 128) ? 2 : 4;
    constexpr int WN = 8 / WM;
    constexpr int MF = 128 / (WM * 16);
    constexpr int NF = NN / (WN * 8);
    constexpr int PITCH = 144;
    constexpr int ABYTES = 128 * PITCH;
    constexpr int BBYTES = NN * PITCH;

    extern __shared__ __align__(16) char smem[];
    const uint32_t sb = smem_u32(smem);
    const uint32_t sA[2] = {sb, sb + ABYTES};
    const uint32_t sB[2] = {sb + 2 * ABYTES, sb + 2 * ABYTES + BBYTES};
    __shared__ float ssum[NN], ssq[NN];

    const int tid = threadIdx.x;
    const int wid = tid >> 5;
    const int lane = tid & 31;
    const int m0 = blockIdx.x * 128;
    const int wmb = (wid / WN) * (MF * 16);
    const int wnb = (wid % WN) * (NF * 8);

    float acc[MF][NF][4];
    #pragma unroll
    for (int i = 0; i < MF; i++)
        #pragma unroll
        for (int j = 0; j < NF; j++)
            #pragma unroll
            for (int k = 0; k < 4; k++) acc[i][j][k] = 0.f;

    auto load_tile = [&](int it) {
        int buf = it & 1;
        const __half* As = (it >> 2) ? Xf : Af;
        int kh = it & 1;
        #pragma unroll
        for (int u = 0; u < 4; u++) {
            int unit = tid + u * 256;
            int row = unit >> 3, cu = unit & 7;
            int m = m0 + row;
            cpa16(sA[buf] + row * PITCH + cu * 16,
                  (const char*)(As + (size_t)m * C + kh * 64) + cu * 16,
                  (m < N_NODES) ? 16u : 0u);
        }
        const char* Bs = (const char*)(Bt + (size_t)it * NN * 64);
        #pragma unroll
        for (int u = 0; u < NN / 32; u++) {
            int unit = tid + u * 256;
            int n = unit >> 3, cu = unit & 7;
            cpa16(sB[buf] + n * PITCH + cu * 16, Bs + n * 128 + cu * 16, 16u);
        }
    };

    const uint32_t a_lane = (lane & 7) * PITCH + ((lane >> 3) & 1) * 8 * PITCH + (lane >> 4) * 16;
    const uint32_t b_lane = (lane & 7) * PITCH + (((lane & 15) >> 3)) * 16;

    load_tile(0);
    CP_COMMIT();
    for (int it = 0; it < 8; it++) {
        if (it < 7) {
            load_tile(it + 1);
            CP_COMMIT();
            asm volatile("cp.async.wait_group 1;" ::: "memory");
        } else {
            asm volatile("cp.async.wait_group 0;" ::: "memory");
        }
        __syncthreads();
        uint32_t abase = sA[it & 1] + wmb * PITCH + a_lane;
        uint32_t bbase = sB[it & 1] + wnb * PITCH + b_lane;
        #pragma unroll
        for (int ks = 0; ks < 4; ks++) {
            uint32_t a[MF][4], b[NF][2];
            #pragma unroll
            for (int mf = 0; mf < MF; mf++) ldsm_x4(a[mf], abase + mf * 16 * PITCH + ks * 32);
            #pragma unroll
            for (int nf = 0; nf < NF; nf++) ldsm_x2(b[nf], bbase + nf * 8 * PITCH + ks * 32);
            #pragma unroll
            for (int mf = 0; mf < MF; mf++)
                #pragma unroll
                for (int nf = 0; nf < NF; nf++) mma16816(acc[mf][nf], a[mf], b[nf]);
        }
        __syncthreads();
    }

    if (STATS) {
        if (tid < NN) { ssum[tid] = 0.f; ssq[tid] = 0.f; }
        __syncthreads();
    }

    #pragma unroll
    for (int mf = 0; mf < MF; mf++) {
        int r = m0 + wmb + mf * 16 + (lane >> 2);
        #pragma unroll
        for (int nf = 0; nf < NF; nf++) {
            int cc = wnb + nf * 8 + (lane & 3) * 2;
            float b0 = bias ? bias[cc] : 0.f;
            float b1 = bias ? bias[cc + 1] : 0.f;
            if (r < N_NODES)
                *(float2*)(H + (size_t)r * NN + cc) =
                    make_float2(acc[mf][nf][0] + b0, acc[mf][nf][1] + b1);
            if (r + 8 < N_NODES)
                *(float2*)(H + (size_t)(r + 8) * NN + cc) =
                    make_float2(acc[mf][nf][2] + b0, acc[mf][nf][3] + b1);
        }
    }

    if (STATS) {
        // OOB rows hold zeros (cp.async zfill) -> contribute nothing
        #pragma unroll
        for (int nf = 0; nf < NF; nf++) {
            #pragma unroll
            for (int j = 0; j < 2; j++) {
                int col = wnb + nf * 8 + (lane & 3) * 2 + j;
                float s = 0.f, q = 0.f;
                #pragma unroll
                for (int mf = 0; mf < MF; mf++) {
                    float v0 = acc[mf][nf][j];
                    float v1 = acc[mf][nf][2 + j];
                    s += v0 + v1;
                    q += v0 * v0 + v1 * v1;
                }
                atomicAdd(&ssum[col], s);
                atomicAdd(&ssq[col], q);
            }
        }
        __syncthreads();
        if (tid < NN) {
            atomicAdd(&g_sum[layer * C + tid], ssum[tid]);
            atomicAdd(&g_sumsq[layer * C + tid], ssq[tid]);
        }
    }
}

// ================= BN apply (finalize fused): in-place fp16 feature update =================
__global__ void bn_apply_kernel(const float* __restrict__ h,
                                const float* __restrict__ gamma,
                                const float* __restrict__ beta, int layer) {
    int i = blockIdx.x * blockDim.x + threadIdx.x;
    if (i >= N_NODES * (C / 4)) return;
    int c = (i & 31) << 2;
    float4 sm = *(const float4*)(g_sum + layer * C + c);
    float4 sq = *(const float4*)(g_sumsq + layer * C + c);
    float4 gm = *(const float4*)(gamma + c);
    float4 bt = *(const float4*)(beta + c);
    const float inv = 1.f / N_NODES;
    float mx = sm.x * inv, my = sm.y * inv, mz = sm.z * inv, mw = sm.w * inv;
    float scx = gm.x * rsqrtf(sq.x * inv - mx * mx + BN_EPS);
    float scy = gm.y * rsqrtf(sq.y * inv - my * my + BN_EPS);
    float scz = gm.z * rsqrtf(sq.z * inv - mz * mz + BN_EPS);
    float scw = gm.w * rsqrtf(sq.w * inv - mw * mw + BN_EPS);
    float shx = bt.x - mx * scx, shy = bt.y - my * scy;
    float shz = bt.z - mz * scz, shw = bt.w - mw * scw;

    float4 hv = ((const float4*)h)[i];
    uint2 xr = *(const uint2*)(g_xf + (size_t)i * 4);
    float2 xa = h2f2(xr.x), xb = h2f2(xr.y);
    float4 o;
    o.x = fmaxf(fmaf(hv.x, scx, shx) + xa.x, 0.f);
    o.y = fmaxf(fmaf(hv.y, scy, shy) + xa.y, 0.f);
    o.z = fmaxf(fmaf(hv.z, scz, shz) + xb.x, 0.f);
    o.w = fmaxf(fmaf(hv.w, scw, shw) + xb.y, 0.f);
    half_store4(o, g_xf + (size_t)i * 4);
}

// ================= launch =================
extern "C" void kernel_launch(void* const* d_in, const int* in_sizes, int n_in,
                              void* d_out, int out_size) {
    const float* x    = (const float*)d_in[0];
    const int*   esrc = (const int*)d_in[1];
    const int*   edst = (const int*)d_in[2];
    const float* ew   = (const float*)d_in[3];
    const float* Wr0  = (const float*)d_in[4];
    // b_rel0 (d_in[5]) cancels exactly under BN
    const float* Wo0  = (const float*)d_in[6];
    const float* Wr1  = (const float*)d_in[7];
    // b_rel1 (d_in[8]) cancels under BN
    const float* Wo1  = (const float*)d_in[9];
    const float* Wr2  = (const float*)d_in[10];
    const float* b2   = (const float*)d_in[11];
    const float* Wo2  = (const float*)d_in[12];
    const float* gamma0 = (const float*)d_in[13];
    const float* beta0  = (const float*)d_in[14];
    const float* gamma1 = (const float*)d_in[15];
    const float* beta1  = (const float*)d_in[16];
    float* out = (float*)d_out;

    float* h;
    __half *aggf, *xf, *bt0, *bt1, *bt2;
    cudaGetSymbolAddress((void**)&h, g_h);
    cudaGetSymbolAddress((void**)&aggf, g_aggf);
    cudaGetSymbolAddress((void**)&xf, g_xf);
    cudaGetSymbolAddress((void**)&bt0, g_bt0);
    cudaGetSymbolAddress((void**)&bt1, g_bt1);
    cudaGetSymbolAddress((void**)&bt2, g_bt2);

    const int SMEM128 = 2 * 128 * 144 + 2 * 128 * 144;  // 73728
    const int SMEM64  = 2 * 128 * 144 + 2 * 64 * 144;   // 55296
    cudaFuncSetAttribute(mma_gemm_kernel<128, true>,
                         cudaFuncAttributeMaxDynamicSharedMemorySize, SMEM128);
    cudaFuncSetAttribute(mma_gemm_kernel<64, false>,
                         cudaFuncAttributeMaxDynamicSharedMemorySize, SMEM64);

    const int EB = (N_EDGES + 255) / 256;
    const int AGG_B = (N_NODES + 7) / 8;
    const int GEMM_B = (N_NODES + 127) / 128;
    const int APPLY_B = (N_NODES * (C / 4) + 255) / 256;
    const int BT_TOTAL = 2 * (8 * 128 * 64) + 8 * 64 * 64;

    setup_kernel<<<APPLY_B, 256>>>(x);
    hist_kernel<<<EB, 256>>>(edst);
    scan_kernel<<<1, 1024>>>();
    build_csr_kernel<<<EB, 256>>>(esrc, edst, ew);
    build_bt_all<<<(BT_TOTAL + 255) / 256, 256>>>(Wr0, Wo0, Wr1, Wo1, Wr2, Wo2);

    // ---- layer 0 ----
    aggregate_kernel<<<AGG_B, 256>>>();
    mma_gemm_kernel<128, true><<<GEMM_B, 256, SMEM128>>>(aggf, xf, bt0, nullptr, h, 0);
    bn_apply_kernel<<<APPLY_B, 256>>>(h, gamma0, beta0, 0);

    // ---- layer 1 ----
    aggregate_kernel<<<AGG_B, 256>>>();
    mma_gemm_kernel<128, true><<<GEMM_B, 256, SMEM128>>>(aggf, xf, bt1, nullptr, h, 1);
    bn_apply_kernel<<<APPLY_B, 256>>>(h, gamma1, beta1, 1);

    // ---- layer 2 ----
    aggregate_kernel<<<AGG_B, 256>>>();
    mma_gemm_kernel<64, false><<<GEMM_B, 256, SMEM64>>>(aggf, xf, bt2, b2, out, 0);
}